// round 15
// baseline (speedup 1.0000x reference)
#include <cuda_runtime.h>
#include <cuda_bf16.h>
#include <cstdint>

#define BB   128
#define TT   1024
#define HH   512
#define IIN  17
#define OOUT 17
#define NBLK 128
#define NTHR 512

#define BSLOT_U32 (32 * 128 * 16)      // 65536 u32 = 256KB per slot
#define AMAT_U16 (128 * 32 * 32 * 16)  // 4MB

typedef unsigned int u32;
typedef unsigned short u16;

// ---------------- device scratch ----------------
__device__ u16 g_A0 [AMAT_U16];                     // whh0 split, frag order
__device__ u16 g_A1i[AMAT_U16];                     // wih1 split
__device__ u16 g_A1h[AMAT_U16];                     // whh1 split
__device__ u32 g_y0b[(size_t)(TT + 1) * BSLOT_U32]; // layer0 h history
__device__ u32 g_h1b[(size_t)(TT + 1) * BSLOT_U32]; // layer1 h history

__device__ unsigned g_root = 0;                     // monotonic arrival counter
__device__ unsigned g_flag[NBLK * 32];              // per-block release flags (128B stride)
__device__ unsigned g_done = 0;

// ---------------- broadcast-flag grid barrier (monotonic) ----------------
// Arrival: one atomicAdd on the shared counter. The LAST arriver of round
// `rnd` broadcasts `rnd` to every block's private flag line, so waiters
// poll an uncontended address.
__device__ __forceinline__ void bar_arrive(unsigned rnd)
{
    __threadfence();
    unsigned old = atomicAdd(&g_root, 1u);
    if (old == rnd * NBLK - 1u) {
        __threadfence();
#pragma unroll 4
        for (int b2 = 0; b2 < NBLK; ++b2)
            *(volatile unsigned*)&g_flag[b2 * 32] = rnd;
    }
}
__device__ __forceinline__ void bar_wait(unsigned rnd)
{
    while (*(volatile unsigned*)&g_flag[blockIdx.x * 32] < rnd) { }
    __threadfence();
}
__device__ __forceinline__ void barrier_epilogue()
{
    if (threadIdx.x == 0) {
        __threadfence();
        atomicAdd(&g_done, 1u);
        if (blockIdx.x == 0) {
            while (*(volatile unsigned*)&g_done < NBLK) { }
            for (int b2 = 0; b2 < NBLK; ++b2) g_flag[b2 * 32] = 0;
            g_root = 0;
            g_done = 0;
            __threadfence();
        }
    }
}

// ---------------- bf16 helpers ----------------
__device__ __forceinline__ u16 bf16_bits(float v)
{
    return __bfloat16_as_ushort(__float2bfloat16_rn(v));
}
__device__ __forceinline__ float bf16_val(u16 b)
{
    return __bfloat162float(__ushort_as_bfloat16(b));
}
__device__ __forceinline__ uint2 split_bf16(float w)
{
    u16 hb = bf16_bits(w);
    float r = w - bf16_val(hb);
    u16 lb = bf16_bits(r);
    return make_uint2(hb, lb);
}

__device__ __forceinline__ void mma_bf16(float c[4], const float4& a,
                                         float b0, float b1)
{
    asm("mma.sync.aligned.m16n8k16.row.col.f32.bf16.bf16.f32 "
        "{%0,%1,%2,%3}, {%4,%5,%6,%7}, {%8,%9}, {%0,%1,%2,%3};"
        : "+f"(c[0]), "+f"(c[1]), "+f"(c[2]), "+f"(c[3])
        : "r"(__float_as_uint(a.x)), "r"(__float_as_uint(a.y)),
          "r"(__float_as_uint(a.z)), "r"(__float_as_uint(a.w)),
          "r"(__float_as_uint(b0)), "r"(__float_as_uint(b1)));
}

__device__ __forceinline__ float sigf(float v)
{
    return __fdividef(1.f, 1.f + __expf(-v));
}
__device__ __forceinline__ float tanhf_fast(float v)
{
    return 1.f - __fdividef(2.f, __expf(2.f * v) + 1.f);
}

#define BAR_GRP(id) asm volatile("bar.sync %0, 256;" :: "r"(id) : "memory")

// ---------------- weight prep: bf16 split + m16n8k16 fragment reorder --------
extern "C" __global__ void prep_weights(const float* __restrict__ whh0,
                                        const float* __restrict__ wih1,
                                        const float* __restrict__ whh1)
{
    const int ME = 2048 * 512;
    int idx = blockIdx.x * blockDim.x + threadIdx.x;
    if (idx >= 3 * ME) return;
    int mat = idx / ME, e = idx % ME;
    int mp = e >> 9, k = e & 511;
    int cell = mp >> 2, g = mp & 3;
    const float* W = (mat == 0) ? whh0 : (mat == 1) ? wih1 : whh1;
    uint2 s = split_bf16(W[(size_t)(g * HH + cell) * HH + k]);

    int mt = mp >> 4, rl = mp & 15;
    int gi = rl & 7, mhalf = rl >> 3;
    int kt = k >> 4, kk = k & 15;
    int ti = (kk & 7) >> 1, khalf = kk >> 3, kbit = kk & 1;
    int areg = mhalf + 2 * khalf;
    int lane = gi * 4 + ti;
    u16* dst = (mat == 0) ? g_A0 : (mat == 1) ? g_A1i : g_A1h;
    size_t base16 = (((size_t)mt * 32 + kt) * 32 + lane) * 16;
    dst[base16 + areg * 2 + kbit]     = (u16)s.x;
    dst[base16 + 8 + areg * 2 + kbit] = (u16)s.y;
}

// ================= fused warp-specialized 2-layer kernel =================
// grid 128 = 64 mb x 2 nb.  Warps 0-7: layer0 step r.  Warps 8-15: layer1 step r-1.
#define GSMC 2080
// smem map (bytes):
//   a0hi 0 | a0lo 32768 | a1hi 65536 | a1lo 98304
//   gsmA 131072 (33280) | gsmB 164352 (33280) | hsmA 197632 (2048) | hsmB 199680 (2048)
//   cb0 201728 | cb1 201856 | Wi0 201984 (2176) | Xs 204160 (4352) | end 208512
#define SMEM_BYTES 208512

__device__ __forceinline__ void store_gsm4(float* gbase, float acc[2][4][4],
                                           int wk, int wn, int gi, int ti)
{
    float* g = gbase + wk * GSMC;
#pragma unroll
    for (int mt = 0; mt < 2; ++mt) {
        int r0 = mt * 16 + gi;
#pragma unroll
        for (int nt = 0; nt < 4; ++nt) {
            int col = wn * 32 + nt * 8 + 2 * ti;
            g[r0 * 65 + col]           = acc[mt][nt][0];
            g[r0 * 65 + col + 1]       = acc[mt][nt][1];
            g[(r0 + 8) * 65 + col]     = acc[mt][nt][2];
            g[(r0 + 8) * 65 + col + 1] = acc[mt][nt][3];
        }
    }
}

extern "C" __global__ void __launch_bounds__(NTHR, 1)
lstm_fused(const float* __restrict__ x,
           const float* __restrict__ wih0,
           const float* __restrict__ bih0, const float* __restrict__ bhh0,
           const float* __restrict__ bih1, const float* __restrict__ bhh1)
{
    extern __shared__ char smc[];
    float4* a0hi4 = (float4*)smc;
    float4* a0lo4 = (float4*)(smc + 32768);
    float4* a1hi4 = (float4*)(smc + 65536);
    float4* a1lo4 = (float4*)(smc + 98304);
    float*  gsmA  = (float*)(smc + 131072);
    float*  gsmB  = (float*)(smc + 164352);
    u32*    hsmA  = (u32*)(smc + 197632);
    u32*    hsmB  = (u32*)(smc + 199680);
    float*  cb0   = (float*)(smc + 201728);
    float*  cb1   = (float*)(smc + 201856);
    float*  Wi0   = (float*)(smc + 201984);   // [8 cells][4 gates][17]
    float*  Xs    = (float*)(smc + 204160);

    const int tid = threadIdx.x;
    const int lane = tid & 31, wid = tid >> 5;
    const int grp = wid >> 3;                 // 0 = layer0, 1 = layer1
    const int wg = wid & 7;
    const int wn = wg & 1, wk = wg >> 1;      // 2 n-halves x 4 k-groups (8 kt)
    const int gi = lane >> 2, ti = lane & 3;
    const int mb = blockIdx.x >> 1, nb = blockIdx.x & 1;
    const int b0 = nb * 64;
    const int gt = tid & 255;                 // id within group
    const int jj = gt >> 5, bl = gt & 31;     // epilogue: cell jj, batches bl, bl+32
    const int kt0 = mb >> 1, mpar = mb & 1;

    // ---- prologue: A slices -> smem ----
    {
        const float4* s0 = (const float4*)(g_A0  + (size_t)mb * 32768);
        const float4* s1 = (const float4*)(g_A1h + (size_t)mb * 32768);
        for (int i = tid; i < 2048; i += NTHR) {
            a0hi4[i] = s0[2 * i];
            a0lo4[i] = s0[2 * i + 1];
            a1hi4[i] = s1[2 * i];
            a1lo4[i] = s1[2 * i + 1];
        }
    }
    if (tid < 32) {
        int cell = mb * 8 + (tid >> 2), g = tid & 3;
        cb0[tid] = bih0[g * HH + cell] + bhh0[g * HH + cell];
    } else if (tid < 64) {
        int t2 = tid - 32;
        int cell = mb * 8 + (t2 >> 2), g = t2 & 3;
        cb1[t2] = bih1[g * HH + cell] + bhh1[g * HH + cell];
    }
    // wih0 slice -> smem: Wi0[jj*68 + g*17 + k]
    for (int idx = tid; idx < 8 * 4 * IIN; idx += NTHR) {
        int jjj = idx / (4 * IIN), rem = idx - jjj * 4 * IIN;
        int g = rem / IIN, k = rem - g * IIN;
        Wi0[idx] = wih0[(size_t)(g * HH + mb * 8 + jjj) * IIN + k];
    }
    {   // zero slot 0 of both buffers
        int f = tid;
        int pb = f >> 3, pti = (f >> 1) & 3, pwh = f & 1;
        u32 pa = ((u32)(kt0 * 128 + b0 + pb) * 4 + pti) * 4 + pwh * 2 + mpar;
        __stcg(&g_y0b[pa], 0u);
        __stcg(&g_h1b[pa], 0u);
    }
    __syncthreads();
    if (tid == 0) bar_arrive(1);

    float cst[2] = {0.f, 0.f};               // grp 0: c0; grp 1: c1
    const float4* A1i4 = (const float4*)(g_A1i + (size_t)mb * 32768);

    for (int r = 0; r <= TT; ++r) {
        const unsigned rnd = (unsigned)r + 1u;
        // stage x_r by group 0 (overlaps barrier wait issue)
        if (grp == 0 && r < TT) {
            for (int idx = gt; idx < 64 * IIN; idx += 256) {
                int rr = idx / IIN, k = idx - rr * IIN;
                Xs[idx] = x[((size_t)(b0 + rr) * TT + r) * IIN + k];
            }
        }
        if (tid == 0) bar_wait(rnd);
        __syncthreads();

        if (grp == 0) {
            // ================= layer0 step r =================
            if (r < TT) {
                float acc[2][4][4];
#pragma unroll
                for (int mt = 0; mt < 2; ++mt)
#pragma unroll
                    for (int nt = 0; nt < 4; ++nt)
#pragma unroll
                        for (int i = 0; i < 4; ++i) acc[mt][nt][i] = 0.f;

                const float4* Bt = (const float4*)(g_y0b + (size_t)r * BSLOT_U32);
#pragma unroll 2
                for (int kt = 0; kt < 8; ++kt) {
                    int ktg = wk * 8 + kt;
                    float4 ah0 = a0hi4[ktg * 32 + lane];
                    float4 al0 = a0lo4[ktg * 32 + lane];
                    float4 ah1 = a0hi4[(32 + ktg) * 32 + lane];
                    float4 al1 = a0lo4[(32 + ktg) * 32 + lane];
#pragma unroll
                    for (int nt = 0; nt < 4; ++nt) {
                        float4 bv = Bt[(size_t)(ktg * 128 + b0 + wn * 32 + nt * 8 + gi) * 4 + ti];
                        mma_bf16(acc[0][nt], ah0, bv.x, bv.y);
                        mma_bf16(acc[0][nt], ah0, bv.z, bv.w);
                        mma_bf16(acc[0][nt], al0, bv.x, bv.y);
                        mma_bf16(acc[1][nt], ah1, bv.x, bv.y);
                        mma_bf16(acc[1][nt], ah1, bv.z, bv.w);
                        mma_bf16(acc[1][nt], al1, bv.x, bv.y);
                    }
                }
                store_gsm4(gsmA, acc, wk, wn, gi, ti);
                BAR_GRP(1);

                {   // cell update L0: (cell jj, batches bl, bl+32)
                    const float* w = Wi0 + jj * 68;
#pragma unroll
                    for (int u = 0; u < 2; ++u) {
                        int b = bl + u * 32;
                        float s0 = cb0[jj * 4 + 0], s1 = cb0[jj * 4 + 1];
                        float s2 = cb0[jj * 4 + 2], s3 = cb0[jj * 4 + 3];
#pragma unroll
                        for (int c = 0; c < 4; ++c) {
                            const float* g = gsmA + c * GSMC;
                            s0 += g[(jj * 4 + 0) * 65 + b];
                            s1 += g[(jj * 4 + 1) * 65 + b];
                            s2 += g[(jj * 4 + 2) * 65 + b];
                            s3 += g[(jj * 4 + 3) * 65 + b];
                        }
#pragma unroll
                        for (int k = 0; k < IIN; ++k) {
                            float xv = Xs[b * IIN + k];
                            s0 = fmaf(w[k],          xv, s0);
                            s1 = fmaf(w[IIN + k],    xv, s1);
                            s2 = fmaf(w[2 * IIN + k], xv, s2);
                            s3 = fmaf(w[3 * IIN + k], xv, s3);
                        }
                        cst[u] = sigf(s1) * cst[u] + sigf(s0) * tanhf_fast(s2);
                        float h = sigf(s3) * tanhf_fast(cst[u]);
                        uint2 hs = split_bf16(h);
                        hsmA[jj * 64 + b] = hs.x | (hs.y << 16);
                    }
                }
                BAR_GRP(1);

                {   // publish y0 slot r+1 (2 u32 per thread)
#pragma unroll
                    for (int u = 0; u < 2; ++u) {
                        int f = gt + u * 256;
                        int pb = f >> 3, pti = (f >> 1) & 3, pwh = f & 1;
                        u32 pa = ((u32)(kt0 * 128 + b0 + pb) * 4 + pti) * 4 + pwh * 2 + mpar;
                        u32 w0 = hsmA[(2 * pti) * 64 + pb];
                        u32 w1 = hsmA[(2 * pti + 1) * 64 + pb];
                        u32 val = __byte_perm(w0, w1, pwh ? 0x7632 : 0x5410);
                        __stcg(&g_y0b[(size_t)(r + 1) * BSLOT_U32 + pa], val);
                    }
                }
            }
        } else {
            // ================= layer1 step r-1 =================
            if (r >= 1) {
                float acc[2][4][4];
#pragma unroll
                for (int mt = 0; mt < 2; ++mt)
#pragma unroll
                    for (int nt = 0; nt < 4; ++nt)
#pragma unroll
                        for (int i = 0; i < 4; ++i) acc[mt][nt][i] = 0.f;

                // recurrent part: whh1 (smem) x h1[r-1]
                const float4* Bh = (const float4*)(g_h1b + (size_t)(r - 1) * BSLOT_U32);
#pragma unroll 2
                for (int kt = 0; kt < 8; ++kt) {
                    int ktg = wk * 8 + kt;
                    float4 ah0 = a1hi4[ktg * 32 + lane];
                    float4 al0 = a1lo4[ktg * 32 + lane];
                    float4 ah1 = a1hi4[(32 + ktg) * 32 + lane];
                    float4 al1 = a1lo4[(32 + ktg) * 32 + lane];
#pragma unroll
                    for (int nt = 0; nt < 4; ++nt) {
                        float4 bv = Bh[(size_t)(ktg * 128 + b0 + wn * 32 + nt * 8 + gi) * 4 + ti];
                        mma_bf16(acc[0][nt], ah0, bv.x, bv.y);
                        mma_bf16(acc[0][nt], ah0, bv.z, bv.w);
                        mma_bf16(acc[0][nt], al0, bv.x, bv.y);
                        mma_bf16(acc[1][nt], ah1, bv.x, bv.y);
                        mma_bf16(acc[1][nt], ah1, bv.z, bv.w);
                        mma_bf16(acc[1][nt], al1, bv.x, bv.y);
                    }
                }
                // input part: wih1 (L2) x y0[r]
                const float4* By = (const float4*)(g_y0b + (size_t)r * BSLOT_U32);
#pragma unroll 2
                for (int kt = 0; kt < 8; ++kt) {
                    int ktg = wk * 8 + kt;
                    size_t b00 = (size_t)(ktg * 32 + lane) * 2;
                    size_t b10 = (size_t)((32 + ktg) * 32 + lane) * 2;
                    float4 ah0 = __ldg(&A1i4[b00]);
                    float4 al0 = __ldg(&A1i4[b00 + 1]);
                    float4 ah1 = __ldg(&A1i4[b10]);
                    float4 al1 = __ldg(&A1i4[b10 + 1]);
#pragma unroll
                    for (int nt = 0; nt < 4; ++nt) {
                        float4 bv = By[(size_t)(ktg * 128 + b0 + wn * 32 + nt * 8 + gi) * 4 + ti];
                        mma_bf16(acc[0][nt], ah0, bv.x, bv.y);
                        mma_bf16(acc[0][nt], ah0, bv.z, bv.w);
                        mma_bf16(acc[0][nt], al0, bv.x, bv.y);
                        mma_bf16(acc[1][nt], ah1, bv.x, bv.y);
                        mma_bf16(acc[1][nt], ah1, bv.z, bv.w);
                        mma_bf16(acc[1][nt], al1, bv.x, bv.y);
                    }
                }
                store_gsm4(gsmB, acc, wk, wn, gi, ti);
                BAR_GRP(2);

                {   // cell update L1
#pragma unroll
                    for (int u = 0; u < 2; ++u) {
                        int b = bl + u * 32;
                        float s0 = cb1[jj * 4 + 0], s1 = cb1[jj * 4 + 1];
                        float s2 = cb1[jj * 4 + 2], s3 = cb1[jj * 4 + 3];
#pragma unroll
                        for (int c = 0; c < 4; ++c) {
                            const float* g = gsmB + c * GSMC;
                            s0 += g[(jj * 4 + 0) * 65 + b];
                            s1 += g[(jj * 4 + 1) * 65 + b];
                            s2 += g[(jj * 4 + 2) * 65 + b];
                            s3 += g[(jj * 4 + 3) * 65 + b];
                        }
                        cst[u] = sigf(s1) * cst[u] + sigf(s0) * tanhf_fast(s2);
                        float h = sigf(s3) * tanhf_fast(cst[u]);
                        uint2 hs = split_bf16(h);
                        hsmB[jj * 64 + b] = hs.x | (hs.y << 16);
                    }
                }
                BAR_GRP(2);

                {   // publish h1 slot r
#pragma unroll
                    for (int u = 0; u < 2; ++u) {
                        int f = gt + u * 256;
                        int pb = f >> 3, pti = (f >> 1) & 3, pwh = f & 1;
                        u32 pa = ((u32)(kt0 * 128 + b0 + pb) * 4 + pti) * 4 + pwh * 2 + mpar;
                        u32 w0 = hsmB[(2 * pti) * 64 + pb];
                        u32 w1 = hsmB[(2 * pti + 1) * 64 + pb];
                        u32 val = __byte_perm(w0, w1, pwh ? 0x7632 : 0x5410);
                        __stcg(&g_h1b[(size_t)r * BSLOT_U32 + pa], val);
                    }
                }
            }
        }

        __syncthreads();
        if (tid == 0 && r < TT) bar_arrive(rnd + 1u);
    }
    barrier_epilogue();
}

// ---------------- final linear (512 thr, 4-way j split) ----------------
extern "C" __global__ void __launch_bounds__(512)
final_linear(const float* __restrict__ lin_w,
             const float* __restrict__ lin_b,
             float* __restrict__ out)
{
    __shared__ float wrow[HH];
    __shared__ float part[4][128];
    int o = blockIdx.x, tid = threadIdx.x;
    wrow[tid] = lin_w[o * HH + tid];
    __syncthreads();
    int q = tid >> 7, b = tid & 127;
    const u32* hb = g_h1b + (size_t)TT * BSLOT_U32;
    float acc = 0.f;
#pragma unroll 4
    for (int jl = 0; jl < 128; ++jl) {
        int j = q * 128 + jl;
        int kt = j >> 4, kk = j & 15;
        int ti = (kk & 7) >> 1, khalf = kk >> 3, kbit = kk & 1;
        u32 gbase = ((u32)(kt * 128 + b) * 4 + ti) * 4;
        u32 w1 = hb[gbase + khalf];
        u32 w2 = hb[gbase + 2 + khalf];
        u16 b1 = kbit ? (u16)(w1 >> 16) : (u16)(w1 & 0xffff);
        u16 b2 = kbit ? (u16)(w2 >> 16) : (u16)(w2 & 0xffff);
        acc = fmaf(bf16_val(b1) + bf16_val(b2), wrow[j], acc);
    }
    part[q][b] = acc;
    __syncthreads();
    if (q == 0)
        out[b * OOUT + o] = part[0][b] + part[1][b] + part[2][b] + part[3][b]
                          + lin_b[o];
}

// ---------------- launch ----------------
extern "C" void kernel_launch(void* const* d_in, const int* in_sizes, int n_in,
                              void* d_out, int out_size)
{
    const float* x     = (const float*)d_in[0];
    const float* wih0  = (const float*)d_in[1];
    const float* whh0  = (const float*)d_in[2];
    const float* bih0  = (const float*)d_in[3];
    const float* bhh0  = (const float*)d_in[4];
    const float* wih1  = (const float*)d_in[5];
    const float* whh1  = (const float*)d_in[6];
    const float* bih1  = (const float*)d_in[7];
    const float* bhh1  = (const float*)d_in[8];
    const float* lin_w = (const float*)d_in[9];
    const float* lin_b = (const float*)d_in[10];

    cudaFuncSetAttribute(lstm_fused, cudaFuncAttributeMaxDynamicSharedMemorySize, SMEM_BYTES);

    prep_weights<<<(3 * 2048 * 512 + 255) / 256, 256>>>(whh0, wih1, whh1);
    lstm_fused<<<NBLK, NTHR, SMEM_BYTES>>>(x, wih0, bih0, bhh0, bih1, bhh1);
    final_linear<<<OOUT, 512>>>(lin_w, lin_b, (float*)d_out);
}

// round 16
// speedup vs baseline: 1.0907x; 1.0907x over previous
#include <cuda_runtime.h>
#include <cuda_bf16.h>
#include <cstdint>

#define BB   128
#define TT   1024
#define HH   512
#define IIN  17
#define OOUT 17
#define NBLK 128
#define NHALF 64
#define NTHR 512

#define BSLOT_U32 (32 * 128 * 16)      // 65536 u32 = 256KB per slot
#define AMAT_U16 (128 * 32 * 32 * 16)  // 4MB

typedef unsigned int u32;
typedef unsigned short u16;

// ---------------- device scratch ----------------
__device__ u16 g_A0 [AMAT_U16];                     // whh0 split, frag order
__device__ u16 g_A1i[AMAT_U16];                     // wih1 split
__device__ u16 g_A1h[AMAT_U16];                     // whh1 split
__device__ u32 g_y0b[(size_t)(TT + 1) * BSLOT_U32]; // layer0 h history
__device__ u32 g_h1b[(size_t)(TT + 1) * BSLOT_U32]; // layer1 h history

__device__ unsigned g_rootH[2][32];                 // per-half flat counters (128B apart)
__device__ unsigned g_done = 0;

// ---------------- flat one-hop per-half grid barrier (monotonic) ----------------
// The batch halves (nb=0 / nb=1) are fully independent recurrences: each
// block publishes and consumes only its own half's h columns. 64 arrivals
// per barrier instead of 128 halves the L2 atomic serialization.
__device__ __forceinline__ void bar_arrive(unsigned* ctr)
{
    __threadfence();
    atomicAdd(ctr, 1u);
}
__device__ __forceinline__ void bar_wait(unsigned* ctr, unsigned need)
{
    while (*(volatile unsigned*)ctr < need) { }
    __threadfence();
}
__device__ __forceinline__ void barrier_epilogue()
{
    if (threadIdx.x == 0) {
        __threadfence();
        atomicAdd(&g_done, 1u);
        if (blockIdx.x == 0) {
            while (*(volatile unsigned*)&g_done < NBLK) { }
            g_rootH[0][0] = 0;
            g_rootH[1][0] = 0;
            g_done = 0;
            __threadfence();
        }
    }
}

// ---------------- bf16 helpers ----------------
__device__ __forceinline__ u16 bf16_bits(float v)
{
    return __bfloat16_as_ushort(__float2bfloat16_rn(v));
}
__device__ __forceinline__ float bf16_val(u16 b)
{
    return __bfloat162float(__ushort_as_bfloat16(b));
}
__device__ __forceinline__ uint2 split_bf16(float w)
{
    u16 hb = bf16_bits(w);
    float r = w - bf16_val(hb);
    u16 lb = bf16_bits(r);
    return make_uint2(hb, lb);
}

__device__ __forceinline__ void mma_bf16(float c[4], const float4& a,
                                         float b0, float b1)
{
    asm("mma.sync.aligned.m16n8k16.row.col.f32.bf16.bf16.f32 "
        "{%0,%1,%2,%3}, {%4,%5,%6,%7}, {%8,%9}, {%0,%1,%2,%3};"
        : "+f"(c[0]), "+f"(c[1]), "+f"(c[2]), "+f"(c[3])
        : "r"(__float_as_uint(a.x)), "r"(__float_as_uint(a.y)),
          "r"(__float_as_uint(a.z)), "r"(__float_as_uint(a.w)),
          "r"(__float_as_uint(b0)), "r"(__float_as_uint(b1)));
}

__device__ __forceinline__ float sigf(float v)
{
    return __fdividef(1.f, 1.f + __expf(-v));
}
__device__ __forceinline__ float tanhf_fast(float v)
{
    return 1.f - __fdividef(2.f, __expf(2.f * v) + 1.f);
}

#define BAR_GRP(id) asm volatile("bar.sync %0, 256;" :: "r"(id) : "memory")

// ---------------- weight prep: bf16 split + m16n8k16 fragment reorder --------
extern "C" __global__ void prep_weights(const float* __restrict__ whh0,
                                        const float* __restrict__ wih1,
                                        const float* __restrict__ whh1)
{
    const int ME = 2048 * 512;
    int idx = blockIdx.x * blockDim.x + threadIdx.x;
    if (idx >= 3 * ME) return;
    int mat = idx / ME, e = idx % ME;
    int mp = e >> 9, k = e & 511;
    int cell = mp >> 2, g = mp & 3;
    const float* W = (mat == 0) ? whh0 : (mat == 1) ? wih1 : whh1;
    uint2 s = split_bf16(W[(size_t)(g * HH + cell) * HH + k]);

    int mt = mp >> 4, rl = mp & 15;
    int gi = rl & 7, mhalf = rl >> 3;
    int kt = k >> 4, kk = k & 15;
    int ti = (kk & 7) >> 1, khalf = kk >> 3, kbit = kk & 1;
    int areg = mhalf + 2 * khalf;
    int lane = gi * 4 + ti;
    u16* dst = (mat == 0) ? g_A0 : (mat == 1) ? g_A1i : g_A1h;
    size_t base16 = (((size_t)mt * 32 + kt) * 32 + lane) * 16;
    dst[base16 + areg * 2 + kbit]     = (u16)s.x;
    dst[base16 + 8 + areg * 2 + kbit] = (u16)s.y;
}

// ================= fused warp-specialized 2-layer kernel =================
// grid 128 = 64 mb x 2 nb.  Warps 0-7: layer0 step r.  Warps 8-15: layer1 step r-1.
#define GSMC 2080
// smem map (bytes):
//   a0hi 0 | a0lo 32768 | a1hi 65536 | a1lo 98304
//   gsmA 131072 (33280) | gsmB 164352 (33280) | hsmA 197632 (2048) | hsmB 199680 (2048)
//   cb0 201728 | cb1 201856 | Wi0 201984 (2176) | Xs 204160 (4352) | end 208512
#define SMEM_BYTES 208512

__device__ __forceinline__ void store_gsm4(float* gbase, float acc[2][4][4],
                                           int wk, int wn, int gi, int ti)
{
    float* g = gbase + wk * GSMC;
#pragma unroll
    for (int mt = 0; mt < 2; ++mt) {
        int r0 = mt * 16 + gi;
#pragma unroll
        for (int nt = 0; nt < 4; ++nt) {
            int col = wn * 32 + nt * 8 + 2 * ti;
            g[r0 * 65 + col]           = acc[mt][nt][0];
            g[r0 * 65 + col + 1]       = acc[mt][nt][1];
            g[(r0 + 8) * 65 + col]     = acc[mt][nt][2];
            g[(r0 + 8) * 65 + col + 1] = acc[mt][nt][3];
        }
    }
}

extern "C" __global__ void __launch_bounds__(NTHR, 1)
lstm_fused(const float* __restrict__ x,
           const float* __restrict__ wih0,
           const float* __restrict__ bih0, const float* __restrict__ bhh0,
           const float* __restrict__ bih1, const float* __restrict__ bhh1)
{
    extern __shared__ char smc[];
    float4* a0hi4 = (float4*)smc;
    float4* a0lo4 = (float4*)(smc + 32768);
    float4* a1hi4 = (float4*)(smc + 65536);
    float4* a1lo4 = (float4*)(smc + 98304);
    float*  gsmA  = (float*)(smc + 131072);
    float*  gsmB  = (float*)(smc + 164352);
    u32*    hsmA  = (u32*)(smc + 197632);
    u32*    hsmB  = (u32*)(smc + 199680);
    float*  cb0   = (float*)(smc + 201728);
    float*  cb1   = (float*)(smc + 201856);
    float*  Wi0   = (float*)(smc + 201984);   // [8 cells][4 gates][17]
    float*  Xs    = (float*)(smc + 204160);

    const int tid = threadIdx.x;
    const int lane = tid & 31, wid = tid >> 5;
    const int grp = wid >> 3;                 // 0 = layer0, 1 = layer1
    const int wg = wid & 7;
    const int wn = wg & 1, wk = wg >> 1;      // 2 n-halves x 4 k-groups (8 kt)
    const int gi = lane >> 2, ti = lane & 3;
    const int mb = blockIdx.x >> 1, nb = blockIdx.x & 1;
    const int b0 = nb * 64;
    const int gt = tid & 255;                 // id within group
    const int jj = gt >> 5, bl = gt & 31;     // epilogue: cell jj, batches bl, bl+32
    const int kt0 = mb >> 1, mpar = mb & 1;
    unsigned* myctr = &g_rootH[nb][0];

    // ---- prologue: A slices -> smem ----
    {
        const float4* s0 = (const float4*)(g_A0  + (size_t)mb * 32768);
        const float4* s1 = (const float4*)(g_A1h + (size_t)mb * 32768);
        for (int i = tid; i < 2048; i += NTHR) {
            a0hi4[i] = s0[2 * i];
            a0lo4[i] = s0[2 * i + 1];
            a1hi4[i] = s1[2 * i];
            a1lo4[i] = s1[2 * i + 1];
        }
    }
    if (tid < 32) {
        int cell = mb * 8 + (tid >> 2), g = tid & 3;
        cb0[tid] = bih0[g * HH + cell] + bhh0[g * HH + cell];
    } else if (tid < 64) {
        int t2 = tid - 32;
        int cell = mb * 8 + (t2 >> 2), g = t2 & 3;
        cb1[t2] = bih1[g * HH + cell] + bhh1[g * HH + cell];
    }
    // wih0 slice -> smem: Wi0[jj*68 + g*17 + k]
    for (int idx = tid; idx < 8 * 4 * IIN; idx += NTHR) {
        int jjj = idx / (4 * IIN), rem = idx - jjj * 4 * IIN;
        int g = rem / IIN, k = rem - g * IIN;
        Wi0[idx] = wih0[(size_t)(g * HH + mb * 8 + jjj) * IIN + k];
    }
    {   // zero slot 0 of both buffers
        int f = tid;
        int pb = f >> 3, pti = (f >> 1) & 3, pwh = f & 1;
        u32 pa = ((u32)(kt0 * 128 + b0 + pb) * 4 + pti) * 4 + pwh * 2 + mpar;
        __stcg(&g_y0b[pa], 0u);
        __stcg(&g_h1b[pa], 0u);
    }
    __syncthreads();
    if (tid == 0) bar_arrive(myctr);

    float cst[2] = {0.f, 0.f};               // grp 0: c0; grp 1: c1
    unsigned need = NHALF;
    const float4* A1i4 = (const float4*)(g_A1i + (size_t)mb * 32768);

    for (int r = 0; r <= TT; ++r) {
        // stage x_r by group 0 (overlaps barrier wait issue)
        if (grp == 0 && r < TT) {
            for (int idx = gt; idx < 64 * IIN; idx += 256) {
                int rr = idx / IIN, k = idx - rr * IIN;
                Xs[idx] = x[((size_t)(b0 + rr) * TT + r) * IIN + k];
            }
        }
        if (tid == 0) bar_wait(myctr, need);
        __syncthreads();

        if (grp == 0) {
            // ================= layer0 step r =================
            if (r < TT) {
                float acc[2][4][4];
#pragma unroll
                for (int mt = 0; mt < 2; ++mt)
#pragma unroll
                    for (int nt = 0; nt < 4; ++nt)
#pragma unroll
                        for (int i = 0; i < 4; ++i) acc[mt][nt][i] = 0.f;

                const float4* Bt = (const float4*)(g_y0b + (size_t)r * BSLOT_U32);
#pragma unroll 2
                for (int kt = 0; kt < 8; ++kt) {
                    int ktg = wk * 8 + kt;
                    float4 ah0 = a0hi4[ktg * 32 + lane];
                    float4 al0 = a0lo4[ktg * 32 + lane];
                    float4 ah1 = a0hi4[(32 + ktg) * 32 + lane];
                    float4 al1 = a0lo4[(32 + ktg) * 32 + lane];
#pragma unroll
                    for (int nt = 0; nt < 4; ++nt) {
                        float4 bv = Bt[(size_t)(ktg * 128 + b0 + wn * 32 + nt * 8 + gi) * 4 + ti];
                        mma_bf16(acc[0][nt], ah0, bv.x, bv.y);
                        mma_bf16(acc[0][nt], ah0, bv.z, bv.w);
                        mma_bf16(acc[0][nt], al0, bv.x, bv.y);
                        mma_bf16(acc[1][nt], ah1, bv.x, bv.y);
                        mma_bf16(acc[1][nt], ah1, bv.z, bv.w);
                        mma_bf16(acc[1][nt], al1, bv.x, bv.y);
                    }
                }
                store_gsm4(gsmA, acc, wk, wn, gi, ti);
                BAR_GRP(1);

                {   // cell update L0: (cell jj, batches bl, bl+32)
                    const float* w = Wi0 + jj * 68;
#pragma unroll
                    for (int u = 0; u < 2; ++u) {
                        int b = bl + u * 32;
                        float s0 = cb0[jj * 4 + 0], s1 = cb0[jj * 4 + 1];
                        float s2 = cb0[jj * 4 + 2], s3 = cb0[jj * 4 + 3];
#pragma unroll
                        for (int c = 0; c < 4; ++c) {
                            const float* g = gsmA + c * GSMC;
                            s0 += g[(jj * 4 + 0) * 65 + b];
                            s1 += g[(jj * 4 + 1) * 65 + b];
                            s2 += g[(jj * 4 + 2) * 65 + b];
                            s3 += g[(jj * 4 + 3) * 65 + b];
                        }
#pragma unroll
                        for (int k = 0; k < IIN; ++k) {
                            float xv = Xs[b * IIN + k];
                            s0 = fmaf(w[k],           xv, s0);
                            s1 = fmaf(w[IIN + k],     xv, s1);
                            s2 = fmaf(w[2 * IIN + k], xv, s2);
                            s3 = fmaf(w[3 * IIN + k], xv, s3);
                        }
                        cst[u] = sigf(s1) * cst[u] + sigf(s0) * tanhf_fast(s2);
                        float h = sigf(s3) * tanhf_fast(cst[u]);
                        uint2 hs = split_bf16(h);
                        hsmA[jj * 64 + b] = hs.x | (hs.y << 16);
                    }
                }
                BAR_GRP(1);

                {   // publish y0 slot r+1 (2 u32 per thread)
#pragma unroll
                    for (int u = 0; u < 2; ++u) {
                        int f = gt + u * 256;
                        int pb = f >> 3, pti = (f >> 1) & 3, pwh = f & 1;
                        u32 pa = ((u32)(kt0 * 128 + b0 + pb) * 4 + pti) * 4 + pwh * 2 + mpar;
                        u32 w0 = hsmA[(2 * pti) * 64 + pb];
                        u32 w1 = hsmA[(2 * pti + 1) * 64 + pb];
                        u32 val = __byte_perm(w0, w1, pwh ? 0x7632 : 0x5410);
                        __stcg(&g_y0b[(size_t)(r + 1) * BSLOT_U32 + pa], val);
                    }
                }
            }
        } else {
            // ================= layer1 step r-1 =================
            if (r >= 1) {
                float acc[2][4][4];
#pragma unroll
                for (int mt = 0; mt < 2; ++mt)
#pragma unroll
                    for (int nt = 0; nt < 4; ++nt)
#pragma unroll
                        for (int i = 0; i < 4; ++i) acc[mt][nt][i] = 0.f;

                // recurrent part: whh1 (smem) x h1[r-1]
                const float4* Bh = (const float4*)(g_h1b + (size_t)(r - 1) * BSLOT_U32);
#pragma unroll 2
                for (int kt = 0; kt < 8; ++kt) {
                    int ktg = wk * 8 + kt;
                    float4 ah0 = a1hi4[ktg * 32 + lane];
                    float4 al0 = a1lo4[ktg * 32 + lane];
                    float4 ah1 = a1hi4[(32 + ktg) * 32 + lane];
                    float4 al1 = a1lo4[(32 + ktg) * 32 + lane];
#pragma unroll
                    for (int nt = 0; nt < 4; ++nt) {
                        float4 bv = Bh[(size_t)(ktg * 128 + b0 + wn * 32 + nt * 8 + gi) * 4 + ti];
                        mma_bf16(acc[0][nt], ah0, bv.x, bv.y);
                        mma_bf16(acc[0][nt], ah0, bv.z, bv.w);
                        mma_bf16(acc[0][nt], al0, bv.x, bv.y);
                        mma_bf16(acc[1][nt], ah1, bv.x, bv.y);
                        mma_bf16(acc[1][nt], ah1, bv.z, bv.w);
                        mma_bf16(acc[1][nt], al1, bv.x, bv.y);
                    }
                }
                // input part: wih1 (L2) x y0[r]
                const float4* By = (const float4*)(g_y0b + (size_t)r * BSLOT_U32);
#pragma unroll 2
                for (int kt = 0; kt < 8; ++kt) {
                    int ktg = wk * 8 + kt;
                    size_t b00 = (size_t)(ktg * 32 + lane) * 2;
                    size_t b10 = (size_t)((32 + ktg) * 32 + lane) * 2;
                    float4 ah0 = __ldg(&A1i4[b00]);
                    float4 al0 = __ldg(&A1i4[b00 + 1]);
                    float4 ah1 = __ldg(&A1i4[b10]);
                    float4 al1 = __ldg(&A1i4[b10 + 1]);
#pragma unroll
                    for (int nt = 0; nt < 4; ++nt) {
                        float4 bv = By[(size_t)(ktg * 128 + b0 + wn * 32 + nt * 8 + gi) * 4 + ti];
                        mma_bf16(acc[0][nt], ah0, bv.x, bv.y);
                        mma_bf16(acc[0][nt], ah0, bv.z, bv.w);
                        mma_bf16(acc[0][nt], al0, bv.x, bv.y);
                        mma_bf16(acc[1][nt], ah1, bv.x, bv.y);
                        mma_bf16(acc[1][nt], ah1, bv.z, bv.w);
                        mma_bf16(acc[1][nt], al1, bv.x, bv.y);
                    }
                }
                store_gsm4(gsmB, acc, wk, wn, gi, ti);
                BAR_GRP(2);

                {   // cell update L1
#pragma unroll
                    for (int u = 0; u < 2; ++u) {
                        int b = bl + u * 32;
                        float s0 = cb1[jj * 4 + 0], s1 = cb1[jj * 4 + 1];
                        float s2 = cb1[jj * 4 + 2], s3 = cb1[jj * 4 + 3];
#pragma unroll
                        for (int c = 0; c < 4; ++c) {
                            const float* g = gsmB + c * GSMC;
                            s0 += g[(jj * 4 + 0) * 65 + b];
                            s1 += g[(jj * 4 + 1) * 65 + b];
                            s2 += g[(jj * 4 + 2) * 65 + b];
                            s3 += g[(jj * 4 + 3) * 65 + b];
                        }
                        cst[u] = sigf(s1) * cst[u] + sigf(s0) * tanhf_fast(s2);
                        float h = sigf(s3) * tanhf_fast(cst[u]);
                        uint2 hs = split_bf16(h);
                        hsmB[jj * 64 + b] = hs.x | (hs.y << 16);
                    }
                }
                BAR_GRP(2);

                {   // publish h1 slot r
#pragma unroll
                    for (int u = 0; u < 2; ++u) {
                        int f = gt + u * 256;
                        int pb = f >> 3, pti = (f >> 1) & 3, pwh = f & 1;
                        u32 pa = ((u32)(kt0 * 128 + b0 + pb) * 4 + pti) * 4 + pwh * 2 + mpar;
                        u32 w0 = hsmB[(2 * pti) * 64 + pb];
                        u32 w1 = hsmB[(2 * pti + 1) * 64 + pb];
                        u32 val = __byte_perm(w0, w1, pwh ? 0x7632 : 0x5410);
                        __stcg(&g_h1b[(size_t)r * BSLOT_U32 + pa], val);
                    }
                }
            }
        }

        __syncthreads();
        if (tid == 0 && r < TT) bar_arrive(myctr);
        need += NHALF;
    }
    barrier_epilogue();
}

// ---------------- final linear (512 thr, 4-way j split) ----------------
extern "C" __global__ void __launch_bounds__(512)
final_linear(const float* __restrict__ lin_w,
             const float* __restrict__ lin_b,
             float* __restrict__ out)
{
    __shared__ float wrow[HH];
    __shared__ float part[4][128];
    int o = blockIdx.x, tid = threadIdx.x;
    wrow[tid] = lin_w[o * HH + tid];
    __syncthreads();
    int q = tid >> 7, b = tid & 127;
    const u32* hb = g_h1b + (size_t)TT * BSLOT_U32;
    float acc = 0.f;
#pragma unroll 4
    for (int jl = 0; jl < 128; ++jl) {
        int j = q * 128 + jl;
        int kt = j >> 4, kk = j & 15;
        int ti = (kk & 7) >> 1, khalf = kk >> 3, kbit = kk & 1;
        u32 gbase = ((u32)(kt * 128 + b) * 4 + ti) * 4;
        u32 w1 = hb[gbase + khalf];
        u32 w2 = hb[gbase + 2 + khalf];
        u16 b1 = kbit ? (u16)(w1 >> 16) : (u16)(w1 & 0xffff);
        u16 b2 = kbit ? (u16)(w2 >> 16) : (u16)(w2 & 0xffff);
        acc = fmaf(bf16_val(b1) + bf16_val(b2), wrow[j], acc);
    }
    part[q][b] = acc;
    __syncthreads();
    if (q == 0)
        out[b * OOUT + o] = part[0][b] + part[1][b] + part[2][b] + part[3][b]
                          + lin_b[o];
}

// ---------------- launch ----------------
extern "C" void kernel_launch(void* const* d_in, const int* in_sizes, int n_in,
                              void* d_out, int out_size)
{
    const float* x     = (const float*)d_in[0];
    const float* wih0  = (const float*)d_in[1];
    const float* whh0  = (const float*)d_in[2];
    const float* bih0  = (const float*)d_in[3];
    const float* bhh0  = (const float*)d_in[4];
    const float* wih1  = (const float*)d_in[5];
    const float* whh1  = (const float*)d_in[6];
    const float* bih1  = (const float*)d_in[7];
    const float* bhh1  = (const float*)d_in[8];
    const float* lin_w = (const float*)d_in[9];
    const float* lin_b = (const float*)d_in[10];

    cudaFuncSetAttribute(lstm_fused, cudaFuncAttributeMaxDynamicSharedMemorySize, SMEM_BYTES);

    prep_weights<<<(3 * 2048 * 512 + 255) / 256, 256>>>(whh0, wih1, whh1);
    lstm_fused<<<NBLK, NTHR, SMEM_BYTES>>>(x, wih0, bih0, bhh0, bih1, bhh1);
    final_linear<<<OOUT, 512>>>(lin_w, lin_b, (float*)d_out);
}

// round 17
// speedup vs baseline: 1.2355x; 1.1327x over previous
#include <cuda_runtime.h>
#include <cuda_bf16.h>
#include <cstdint>

#define BB   128
#define TT   1024
#define HH   512
#define IIN  17
#define OOUT 17
#define NBLK 128
#define NHALF 64
#define NTHR 512

#define BSLOT_U32 (32 * 128 * 16)      // 65536 u32 = 256KB per slot
#define AMAT_U16 (128 * 32 * 32 * 16)  // 4MB

typedef unsigned int u32;
typedef unsigned short u16;

// ---------------- device scratch ----------------
__device__ u16 g_A0 [AMAT_U16];                     // whh0 split, frag order
__device__ u16 g_A1i[AMAT_U16];                     // wih1 split
__device__ u16 g_A1h[AMAT_U16];                     // whh1 split
__device__ u32 g_y0b[(size_t)(TT + 1) * BSLOT_U32]; // layer0 h history
__device__ u32 g_h1b[(size_t)(TT + 1) * BSLOT_U32]; // layer1 h history

// per-layer, per-half arrival counters (128B apart)
__device__ unsigned g_cy0[2][32];
__device__ unsigned g_ch1[2][32];
__device__ unsigned g_done = 0;

__device__ __forceinline__ void bar_arrive(unsigned* ctr)
{
    __threadfence();
    atomicAdd(ctr, 1u);
}
__device__ __forceinline__ void bar_wait(unsigned* ctr, unsigned need)
{
    while (*(volatile unsigned*)ctr < need) { }
    __threadfence();
}
__device__ __forceinline__ void barrier_epilogue()
{
    if (threadIdx.x == 0) {
        __threadfence();
        atomicAdd(&g_done, 1u);
        if (blockIdx.x == 0) {
            while (*(volatile unsigned*)&g_done < NBLK) { }
            g_cy0[0][0] = 0; g_cy0[1][0] = 0;
            g_ch1[0][0] = 0; g_ch1[1][0] = 0;
            g_done = 0;
            __threadfence();
        }
    }
}

// ---------------- bf16 helpers ----------------
__device__ __forceinline__ u16 bf16_bits(float v)
{
    return __bfloat16_as_ushort(__float2bfloat16_rn(v));
}
__device__ __forceinline__ float bf16_val(u16 b)
{
    return __bfloat162float(__ushort_as_bfloat16(b));
}
__device__ __forceinline__ uint2 split_bf16(float w)
{
    u16 hb = bf16_bits(w);
    float r = w - bf16_val(hb);
    u16 lb = bf16_bits(r);
    return make_uint2(hb, lb);
}

__device__ __forceinline__ void mma_bf16(float c[4], const float4& a,
                                         float b0, float b1)
{
    asm("mma.sync.aligned.m16n8k16.row.col.f32.bf16.bf16.f32 "
        "{%0,%1,%2,%3}, {%4,%5,%6,%7}, {%8,%9}, {%0,%1,%2,%3};"
        : "+f"(c[0]), "+f"(c[1]), "+f"(c[2]), "+f"(c[3])
        : "r"(__float_as_uint(a.x)), "r"(__float_as_uint(a.y)),
          "r"(__float_as_uint(a.z)), "r"(__float_as_uint(a.w)),
          "r"(__float_as_uint(b0)), "r"(__float_as_uint(b1)));
}

__device__ __forceinline__ float sigf(float v)
{
    return __fdividef(1.f, 1.f + __expf(-v));
}
__device__ __forceinline__ float tanhf_fast(float v)
{
    return 1.f - __fdividef(2.f, __expf(2.f * v) + 1.f);
}

#define BAR_GRP(id) asm volatile("bar.sync %0, 256;" :: "r"(id) : "memory")

// ---------------- weight prep: bf16 split + m16n8k16 fragment reorder --------
extern "C" __global__ void prep_weights(const float* __restrict__ whh0,
                                        const float* __restrict__ wih1,
                                        const float* __restrict__ whh1)
{
    const int ME = 2048 * 512;
    int idx = blockIdx.x * blockDim.x + threadIdx.x;
    if (idx >= 3 * ME) return;
    int mat = idx / ME, e = idx % ME;
    int mp = e >> 9, k = e & 511;
    int cell = mp >> 2, g = mp & 3;
    const float* W = (mat == 0) ? whh0 : (mat == 1) ? wih1 : whh1;
    uint2 s = split_bf16(W[(size_t)(g * HH + cell) * HH + k]);

    int mt = mp >> 4, rl = mp & 15;
    int gi = rl & 7, mhalf = rl >> 3;
    int kt = k >> 4, kk = k & 15;
    int ti = (kk & 7) >> 1, khalf = kk >> 3, kbit = kk & 1;
    int areg = mhalf + 2 * khalf;
    int lane = gi * 4 + ti;
    u16* dst = (mat == 0) ? g_A0 : (mat == 1) ? g_A1i : g_A1h;
    size_t base16 = (((size_t)mt * 32 + kt) * 32 + lane) * 16;
    dst[base16 + areg * 2 + kbit]     = (u16)s.x;
    dst[base16 + 8 + areg * 2 + kbit] = (u16)s.y;
}

// ================= decoupled warp-specialized 2-layer kernel =================
// grid 128 = 64 mb x 2 nb.  Warps 0-7: layer0 ring.  Warps 8-15: layer1 ring.
#define GSMC 2080
// smem map (bytes):
//   a0hi 0 | a0lo 32768 | a1hi 65536 | a1lo 98304
//   gsmA 131072 (33280) | gsmB 164352 (33280) | hsmA 197632 (2048) | hsmB 199680 (2048)
//   cb0 201728 | cb1 201856 | Wi0 201984 (2176) | Xs 204160 (4352) | end 208512
#define SMEM_BYTES 208512

__device__ __forceinline__ void store_gsm4(float* gbase, float acc[2][4][4],
                                           int wk, int wn, int gi, int ti)
{
    float* g = gbase + wk * GSMC;
#pragma unroll
    for (int mt = 0; mt < 2; ++mt) {
        int r0 = mt * 16 + gi;
#pragma unroll
        for (int nt = 0; nt < 4; ++nt) {
            int col = wn * 32 + nt * 8 + 2 * ti;
            g[r0 * 65 + col]           = acc[mt][nt][0];
            g[r0 * 65 + col + 1]       = acc[mt][nt][1];
            g[(r0 + 8) * 65 + col]     = acc[mt][nt][2];
            g[(r0 + 8) * 65 + col + 1] = acc[mt][nt][3];
        }
    }
}

extern "C" __global__ void __launch_bounds__(NTHR, 1)
lstm_fused(const float* __restrict__ x,
           const float* __restrict__ wih0,
           const float* __restrict__ bih0, const float* __restrict__ bhh0,
           const float* __restrict__ bih1, const float* __restrict__ bhh1)
{
    extern __shared__ char smc[];
    float4* a0hi4 = (float4*)smc;
    float4* a0lo4 = (float4*)(smc + 32768);
    float4* a1hi4 = (float4*)(smc + 65536);
    float4* a1lo4 = (float4*)(smc + 98304);
    float*  gsmA  = (float*)(smc + 131072);
    float*  gsmB  = (float*)(smc + 164352);
    u32*    hsmA  = (u32*)(smc + 197632);
    u32*    hsmB  = (u32*)(smc + 199680);
    float*  cb0   = (float*)(smc + 201728);
    float*  cb1   = (float*)(smc + 201856);
    float*  Wi0   = (float*)(smc + 201984);   // [8 cells][4 gates][17]
    float*  Xs    = (float*)(smc + 204160);

    const int tid = threadIdx.x;
    const int lane = tid & 31, wid = tid >> 5;
    const int grp = wid >> 3;                 // 0 = layer0, 1 = layer1
    const int wg = wid & 7;
    const int wn = wg & 1, wk = wg >> 1;      // 2 n-halves x 4 k-groups (8 kt)
    const int gi = lane >> 2, ti = lane & 3;
    const int mb = blockIdx.x >> 1, nb = blockIdx.x & 1;
    const int b0 = nb * 64;
    const int gt = tid & 255;                 // id within group
    const int jj = gt >> 5, bl = gt & 31;     // epilogue: cell jj, batches bl, bl+32
    const int kt0 = mb >> 1, mpar = mb & 1;
    unsigned* cy0 = &g_cy0[nb][0];
    unsigned* ch1 = &g_ch1[nb][0];

    // ---- prologue: A slices -> smem ----
    {
        const float4* s0 = (const float4*)(g_A0  + (size_t)mb * 32768);
        const float4* s1 = (const float4*)(g_A1h + (size_t)mb * 32768);
        for (int i = tid; i < 2048; i += NTHR) {
            a0hi4[i] = s0[2 * i];
            a0lo4[i] = s0[2 * i + 1];
            a1hi4[i] = s1[2 * i];
            a1lo4[i] = s1[2 * i + 1];
        }
    }
    if (tid < 32) {
        int cell = mb * 8 + (tid >> 2), g = tid & 3;
        cb0[tid] = bih0[g * HH + cell] + bhh0[g * HH + cell];
    } else if (tid < 64) {
        int t2 = tid - 32;
        int cell = mb * 8 + (t2 >> 2), g = t2 & 3;
        cb1[t2] = bih1[g * HH + cell] + bhh1[g * HH + cell];
    }
    // wih0 slice -> smem: Wi0[jj*68 + g*17 + k]
    for (int idx = tid; idx < 8 * 4 * IIN; idx += NTHR) {
        int jjj = idx / (4 * IIN), rem = idx - jjj * 4 * IIN;
        int g = rem / IIN, k = rem - g * IIN;
        Wi0[idx] = wih0[(size_t)(g * HH + mb * 8 + jjj) * IIN + k];
    }
    {   // zero slot 0 of both buffers
        int f = tid;
        int pb = f >> 3, pti = (f >> 1) & 3, pwh = f & 1;
        u32 pa = ((u32)(kt0 * 128 + b0 + pb) * 4 + pti) * 4 + pwh * 2 + mpar;
        __stcg(&g_y0b[pa], 0u);
        __stcg(&g_h1b[pa], 0u);
    }
    __syncthreads();
    if (tid == 0)   bar_arrive(cy0);
    if (tid == 256) bar_arrive(ch1);

    float cst[2] = {0.f, 0.f};
    const float4* A1i4 = (const float4*)(g_A1i + (size_t)mb * 32768);

    if (grp == 0) {
        // ================= layer0 ring: rounds r = 0..TT-1 =================
        for (int r = 0; r < TT; ++r) {
            // stage x_r (LDGs issued before the wait)
            for (int idx = gt; idx < 64 * IIN; idx += 256) {
                int rr = idx / IIN, k = idx - rr * IIN;
                Xs[idx] = x[((size_t)(b0 + rr) * TT + r) * IIN + k];
            }
            if (gt == 0) bar_wait(cy0, (unsigned)(r + 1) * NHALF);
            BAR_GRP(1);                               // release group

            float acc[2][4][4];
#pragma unroll
            for (int mt = 0; mt < 2; ++mt)
#pragma unroll
                for (int nt = 0; nt < 4; ++nt)
#pragma unroll
                    for (int i = 0; i < 4; ++i) acc[mt][nt][i] = 0.f;

            const float4* Bt = (const float4*)(g_y0b + (size_t)r * BSLOT_U32);
#pragma unroll 2
            for (int kt = 0; kt < 8; ++kt) {
                int ktg = wk * 8 + kt;
                float4 ah0 = a0hi4[ktg * 32 + lane];
                float4 al0 = a0lo4[ktg * 32 + lane];
                float4 ah1 = a0hi4[(32 + ktg) * 32 + lane];
                float4 al1 = a0lo4[(32 + ktg) * 32 + lane];
#pragma unroll
                for (int nt = 0; nt < 4; ++nt) {
                    float4 bv = Bt[(size_t)(ktg * 128 + b0 + wn * 32 + nt * 8 + gi) * 4 + ti];
                    mma_bf16(acc[0][nt], ah0, bv.x, bv.y);
                    mma_bf16(acc[0][nt], ah0, bv.z, bv.w);
                    mma_bf16(acc[0][nt], al0, bv.x, bv.y);
                    mma_bf16(acc[1][nt], ah1, bv.x, bv.y);
                    mma_bf16(acc[1][nt], ah1, bv.z, bv.w);
                    mma_bf16(acc[1][nt], al1, bv.x, bv.y);
                }
            }
            store_gsm4(gsmA, acc, wk, wn, gi, ti);
            BAR_GRP(1);

            {   // cell update L0: (cell jj, batches bl, bl+32)
                const float* w = Wi0 + jj * 68;
#pragma unroll
                for (int u = 0; u < 2; ++u) {
                    int b = bl + u * 32;
                    float s0 = cb0[jj * 4 + 0], s1 = cb0[jj * 4 + 1];
                    float s2 = cb0[jj * 4 + 2], s3 = cb0[jj * 4 + 3];
#pragma unroll
                    for (int c = 0; c < 4; ++c) {
                        const float* g = gsmA + c * GSMC;
                        s0 += g[(jj * 4 + 0) * 65 + b];
                        s1 += g[(jj * 4 + 1) * 65 + b];
                        s2 += g[(jj * 4 + 2) * 65 + b];
                        s3 += g[(jj * 4 + 3) * 65 + b];
                    }
#pragma unroll
                    for (int k = 0; k < IIN; ++k) {
                        float xv = Xs[b * IIN + k];
                        s0 = fmaf(w[k],           xv, s0);
                        s1 = fmaf(w[IIN + k],     xv, s1);
                        s2 = fmaf(w[2 * IIN + k], xv, s2);
                        s3 = fmaf(w[3 * IIN + k], xv, s3);
                    }
                    cst[u] = sigf(s1) * cst[u] + sigf(s0) * tanhf_fast(s2);
                    float h = sigf(s3) * tanhf_fast(cst[u]);
                    uint2 hs = split_bf16(h);
                    hsmA[jj * 64 + b] = hs.x | (hs.y << 16);
                }
            }
            BAR_GRP(1);

            {   // publish y0 slot r+1 (2 u32 per thread)
#pragma unroll
                for (int u = 0; u < 2; ++u) {
                    int f = gt + u * 256;
                    int pb = f >> 3, pti = (f >> 1) & 3, pwh = f & 1;
                    u32 pa = ((u32)(kt0 * 128 + b0 + pb) * 4 + pti) * 4 + pwh * 2 + mpar;
                    u32 w0 = hsmA[(2 * pti) * 64 + pb];
                    u32 w1 = hsmA[(2 * pti + 1) * 64 + pb];
                    u32 val = __byte_perm(w0, w1, pwh ? 0x7632 : 0x5410);
                    __stcg(&g_y0b[(size_t)(r + 1) * BSLOT_U32 + pa], val);
                }
            }
            BAR_GRP(1);
            if (gt == 0) bar_arrive(cy0);
        }
    } else {
        // ================= layer1 ring: rounds s = 0..TT-1 =================
        for (int s = 0; s < TT; ++s) {
            if (gt == 0) {
                bar_wait(cy0, (unsigned)(s + 2) * NHALF);   // y0 slot s+1 ready
                bar_wait(ch1, (unsigned)(s + 1) * NHALF);   // h1 slot s ready
            }
            BAR_GRP(2);

            float acc[2][4][4];
#pragma unroll
            for (int mt = 0; mt < 2; ++mt)
#pragma unroll
                for (int nt = 0; nt < 4; ++nt)
#pragma unroll
                    for (int i = 0; i < 4; ++i) acc[mt][nt][i] = 0.f;

            // recurrent part: whh1 (smem) x h1[s]
            const float4* Bh = (const float4*)(g_h1b + (size_t)s * BSLOT_U32);
#pragma unroll 2
            for (int kt = 0; kt < 8; ++kt) {
                int ktg = wk * 8 + kt;
                float4 ah0 = a1hi4[ktg * 32 + lane];
                float4 al0 = a1lo4[ktg * 32 + lane];
                float4 ah1 = a1hi4[(32 + ktg) * 32 + lane];
                float4 al1 = a1lo4[(32 + ktg) * 32 + lane];
#pragma unroll
                for (int nt = 0; nt < 4; ++nt) {
                    float4 bv = Bh[(size_t)(ktg * 128 + b0 + wn * 32 + nt * 8 + gi) * 4 + ti];
                    mma_bf16(acc[0][nt], ah0, bv.x, bv.y);
                    mma_bf16(acc[0][nt], ah0, bv.z, bv.w);
                    mma_bf16(acc[0][nt], al0, bv.x, bv.y);
                    mma_bf16(acc[1][nt], ah1, bv.x, bv.y);
                    mma_bf16(acc[1][nt], ah1, bv.z, bv.w);
                    mma_bf16(acc[1][nt], al1, bv.x, bv.y);
                }
            }
            // input part: wih1 (L2) x y0[s+1]
            const float4* By = (const float4*)(g_y0b + (size_t)(s + 1) * BSLOT_U32);
#pragma unroll 2
            for (int kt = 0; kt < 8; ++kt) {
                int ktg = wk * 8 + kt;
                size_t b00 = (size_t)(ktg * 32 + lane) * 2;
                size_t b10 = (size_t)((32 + ktg) * 32 + lane) * 2;
                float4 ah0 = __ldg(&A1i4[b00]);
                float4 al0 = __ldg(&A1i4[b00 + 1]);
                float4 ah1 = __ldg(&A1i4[b10]);
                float4 al1 = __ldg(&A1i4[b10 + 1]);
#pragma unroll
                for (int nt = 0; nt < 4; ++nt) {
                    float4 bv = By[(size_t)(ktg * 128 + b0 + wn * 32 + nt * 8 + gi) * 4 + ti];
                    mma_bf16(acc[0][nt], ah0, bv.x, bv.y);
                    mma_bf16(acc[0][nt], ah0, bv.z, bv.w);
                    mma_bf16(acc[0][nt], al0, bv.x, bv.y);
                    mma_bf16(acc[1][nt], ah1, bv.x, bv.y);
                    mma_bf16(acc[1][nt], ah1, bv.z, bv.w);
                    mma_bf16(acc[1][nt], al1, bv.x, bv.y);
                }
            }
            store_gsm4(gsmB, acc, wk, wn, gi, ti);
            BAR_GRP(2);

            {   // cell update L1
#pragma unroll
                for (int u = 0; u < 2; ++u) {
                    int b = bl + u * 32;
                    float s0 = cb1[jj * 4 + 0], s1 = cb1[jj * 4 + 1];
                    float s2 = cb1[jj * 4 + 2], s3 = cb1[jj * 4 + 3];
#pragma unroll
                    for (int c = 0; c < 4; ++c) {
                        const float* g = gsmB + c * GSMC;
                        s0 += g[(jj * 4 + 0) * 65 + b];
                        s1 += g[(jj * 4 + 1) * 65 + b];
                        s2 += g[(jj * 4 + 2) * 65 + b];
                        s3 += g[(jj * 4 + 3) * 65 + b];
                    }
                    cst[u] = sigf(s1) * cst[u] + sigf(s0) * tanhf_fast(s2);
                    float h = sigf(s3) * tanhf_fast(cst[u]);
                    uint2 hs = split_bf16(h);
                    hsmB[jj * 64 + b] = hs.x | (hs.y << 16);
                }
            }
            BAR_GRP(2);

            {   // publish h1 slot s+1
#pragma unroll
                for (int u = 0; u < 2; ++u) {
                    int f = gt + u * 256;
                    int pb = f >> 3, pti = (f >> 1) & 3, pwh = f & 1;
                    u32 pa = ((u32)(kt0 * 128 + b0 + pb) * 4 + pti) * 4 + pwh * 2 + mpar;
                    u32 w0 = hsmB[(2 * pti) * 64 + pb];
                    u32 w1 = hsmB[(2 * pti + 1) * 64 + pb];
                    u32 val = __byte_perm(w0, w1, pwh ? 0x7632 : 0x5410);
                    __stcg(&g_h1b[(size_t)(s + 1) * BSLOT_U32 + pa], val);
                }
            }
            BAR_GRP(2);
            if (gt == 0) bar_arrive(ch1);
        }
    }

    __syncthreads();
    barrier_epilogue();
}

// ---------------- final linear (512 thr, 4-way j split) ----------------
extern "C" __global__ void __launch_bounds__(512)
final_linear(const float* __restrict__ lin_w,
             const float* __restrict__ lin_b,
             float* __restrict__ out)
{
    __shared__ float wrow[HH];
    __shared__ float part[4][128];
    int o = blockIdx.x, tid = threadIdx.x;
    wrow[tid] = lin_w[o * HH + tid];
    __syncthreads();
    int q = tid >> 7, b = tid & 127;
    const u32* hb = g_h1b + (size_t)TT * BSLOT_U32;
    float acc = 0.f;
#pragma unroll 4
    for (int jl = 0; jl < 128; ++jl) {
        int j = q * 128 + jl;
        int kt = j >> 4, kk = j & 15;
        int ti = (kk & 7) >> 1, khalf = kk >> 3, kbit = kk & 1;
        u32 gbase = ((u32)(kt * 128 + b) * 4 + ti) * 4;
        u32 w1 = hb[gbase + khalf];
        u32 w2 = hb[gbase + 2 + khalf];
        u16 b1 = kbit ? (u16)(w1 >> 16) : (u16)(w1 & 0xffff);
        u16 b2 = kbit ? (u16)(w2 >> 16) : (u16)(w2 & 0xffff);
        acc = fmaf(bf16_val(b1) + bf16_val(b2), wrow[j], acc);
    }
    part[q][b] = acc;
    __syncthreads();
    if (q == 0)
        out[b * OOUT + o] = part[0][b] + part[1][b] + part[2][b] + part[3][b]
                          + lin_b[o];
}

// ---------------- launch ----------------
extern "C" void kernel_launch(void* const* d_in, const int* in_sizes, int n_in,
                              void* d_out, int out_size)
{
    const float* x     = (const float*)d_in[0];
    const float* wih0  = (const float*)d_in[1];
    const float* whh0  = (const float*)d_in[2];
    const float* bih0  = (const float*)d_in[3];
    const float* bhh0  = (const float*)d_in[4];
    const float* wih1  = (const float*)d_in[5];
    const float* whh1  = (const float*)d_in[6];
    const float* bih1  = (const float*)d_in[7];
    const float* bhh1  = (const float*)d_in[8];
    const float* lin_w = (const float*)d_in[9];
    const float* lin_b = (const float*)d_in[10];

    cudaFuncSetAttribute(lstm_fused, cudaFuncAttributeMaxDynamicSharedMemorySize, SMEM_BYTES);

    prep_weights<<<(3 * 2048 * 512 + 255) / 256, 256>>>(whh0, wih1, whh1);
    lstm_fused<<<NBLK, NTHR, SMEM_BYTES>>>(x, wih0, bih0, bhh0, bih1, bhh1);
    final_linear<<<OOUT, 512>>>(lin_w, lin_b, (float*)d_out);
}